// round 16
// baseline (speedup 1.0000x reference)
#include <cuda_runtime.h>

#define FULLMASK 0xffffffffu

static __device__ __forceinline__ float lrelu(float x) { return x > 0.f ? x : 0.2f * x; }

static __device__ __forceinline__ float warpSum(float v) {
#pragma unroll
    for (int o = 16; o; o >>= 1) v += __shfl_xor_sync(FULLMASK, v, o);
    return v;
}
static __device__ __forceinline__ float warpMax(float v) {
#pragma unroll
    for (int o = 16; o; o >>= 1) v = fmaxf(v, __shfl_xor_sync(FULLMASK, v, o));
    return v;
}

static __device__ __forceinline__ float tf32r(float x) {
    unsigned u;
    asm("cvt.rna.tf32.f32 %0, %1;" : "=r"(u) : "f"(x));
    return __uint_as_float(u);
}

static __device__ __forceinline__ void mma_tf32(float* acc,
    unsigned a0, unsigned a1, unsigned a2, unsigned a3, unsigned b0, unsigned b1)
{
    asm volatile(
        "mma.sync.aligned.m16n8k8.row.col.f32.tf32.tf32.f32 "
        "{%0,%1,%2,%3},{%4,%5,%6,%7},{%8,%9},{%0,%1,%2,%3};"
        : "+f"(acc[0]), "+f"(acc[1]), "+f"(acc[2]), "+f"(acc[3])
        : "r"(a0), "r"(a1), "r"(a2), "r"(a3), "r"(b0), "r"(b1));
}

// ---------------- scratch (device globals; no allocation allowed) ----------------
__device__ float g_PQ[2 * 256 * 512];     // P, Qb (fp32 — ep path stays fp32)
__device__ float g_RS[2 * 256 * 512];     // R, Sb
__device__ float g_stat[8 * 256];         // [0..1023]=ep stats, [1024..2047]=ef stats
__device__ float g_t[512 * 256];          // Qt
__device__ float g_dot[256 * 256];        // dotEP (fp32)
__device__ float g_mr[4 * 256 * 256];     // epMean, epRstd, efMean, efRstd
__device__ float g_adj[256 * 256];
__device__ float g_asdp[2 * 256 * 4 * 8]; // per-tile partial a_src/a_dst dots (8 slices)
__device__ float g_asd[2 * 256 * 4];      // summed a_src / a_dst per node
__device__ float g_stats[256 * 8];        // per (i,head): max, 1/Z
__device__ float g_agg[256 * 2048];
__device__ float g_x[256 * 512];
__device__ float g_h[256 * 512];
__device__ float g_w2frag[64 * 16 * 64];      // ef_w2 frags
__device__ float g_w1frag[2 * 64 * 64 * 64];  // ef_w1 frags
__device__ float g_wfrag[3 * 64 * 256 * 64];  // gat_W frags
__device__ float g_sfrag[4 * 32 * 64 * 64];   // s per-head frags
__device__ float g_opfrag[2 * 64 * 64 * 64];  // op_w1 / op_w2 frags

// ------------- fp32 FFMA GEMM, double-buffered (ep path: bit-stable k order) -----
__global__ void __launch_bounds__(256) gemm_kernel(
    const float* __restrict__ A, int lda, long sAz,
    const float* __restrict__ B, int ldb, long sBz,
    float* __restrict__ C, int ldc, long sCz,
    const float* __restrict__ bias, int biasZmask, int K)
{
    __shared__ float As[2][16][65];
    __shared__ float Bs[2][16][68];
    const int z = blockIdx.z;
    A += (long)z * sAz; B += (long)z * sBz; C += (long)z * sCz;
    const int m0 = blockIdx.y * 64, n0 = blockIdx.x * 64;
    const int tid = threadIdx.x;
    const int tx = tid & 15, ty = tid >> 4;
    const int arow = tid >> 2, aseg = tid & 3;
    const int brow = tid >> 4, bseg = tid & 15;
    const float* Aptr = A + (long)(m0 + arow) * lda + aseg * 4;
    const float* Bptr = B + (long)brow * ldb + n0 + bseg * 4;

    float4 av = *(const float4*)(Aptr);
    float4 bv = *(const float4*)(Bptr);
    As[0][aseg * 4 + 0][arow] = av.x;
    As[0][aseg * 4 + 1][arow] = av.y;
    As[0][aseg * 4 + 2][arow] = av.z;
    As[0][aseg * 4 + 3][arow] = av.w;
    *(float4*)&Bs[0][brow][bseg * 4] = bv;
    __syncthreads();

    float acc[4][4] = {};
    int buf = 0;
    for (int k0 = 0; k0 < K; k0 += 16) {
        const bool more = (k0 + 16) < K;
        if (more) {
            av = *(const float4*)(Aptr + k0 + 16);
            bv = *(const float4*)(Bptr + (long)(k0 + 16) * ldb);
        }
#pragma unroll
        for (int kk = 0; kk < 16; kk++) {
            float a[4], b[4];
#pragma unroll
            for (int i2 = 0; i2 < 4; i2++) a[i2] = As[buf][kk][ty * 4 + i2];
            const float4 b4 = *(const float4*)&Bs[buf][kk][tx * 4];
            b[0] = b4.x; b[1] = b4.y; b[2] = b4.z; b[3] = b4.w;
#pragma unroll
            for (int i2 = 0; i2 < 4; i2++)
#pragma unroll
                for (int j2 = 0; j2 < 4; j2++) acc[i2][j2] += a[i2] * b[j2];
        }
        if (more) {
            As[buf ^ 1][aseg * 4 + 0][arow] = av.x;
            As[buf ^ 1][aseg * 4 + 1][arow] = av.y;
            As[buf ^ 1][aseg * 4 + 2][arow] = av.z;
            As[buf ^ 1][aseg * 4 + 3][arow] = av.w;
            *(float4*)&Bs[buf ^ 1][brow][bseg * 4] = bv;
        }
        __syncthreads();
        buf ^= 1;
    }
    const bool addb = bias && ((biasZmask >> z) & 1);
    float4 bb = make_float4(0.f, 0.f, 0.f, 0.f);
    if (addb) bb = *(const float4*)(bias + n0 + tx * 4);
#pragma unroll
    for (int i2 = 0; i2 < 4; i2++) {
        const int m = m0 + ty * 4 + i2;
        float4 v = make_float4(acc[i2][0] + bb.x, acc[i2][1] + bb.y,
                               acc[i2][2] + bb.z, acc[i2][3] + bb.w);
        *(float4*)(C + (long)m * ldc + n0 + tx * 4) = v;
    }
}

// ------- fp32 dot(R_i,S_j) GEMM with transposed-B staging + fused mean/rstd ------
__global__ void __launch_bounds__(256) dotmr_kernel(
    const float* __restrict__ R, const float* __restrict__ S,
    const float* __restrict__ stat,
    float* __restrict__ mrM, float* __restrict__ mrR)
{
    __shared__ float As[2][16][65];
    __shared__ float Bs[2][16][65];
    const int m0 = blockIdx.y * 64, n0 = blockIdx.x * 64;
    const int tid = threadIdx.x;
    const int tx = tid & 15, ty = tid >> 4;
    const int arow = tid >> 2, aseg = tid & 3;
    const float* Aptr = R + (long)(m0 + arow) * 512 + aseg * 4;
    const float* Bptr = S + (long)(n0 + arow) * 512 + aseg * 4;

    float4 av = *(const float4*)Aptr;
    float4 bv = *(const float4*)Bptr;
    As[0][aseg * 4 + 0][arow] = av.x;
    As[0][aseg * 4 + 1][arow] = av.y;
    As[0][aseg * 4 + 2][arow] = av.z;
    As[0][aseg * 4 + 3][arow] = av.w;
    Bs[0][aseg * 4 + 0][arow] = bv.x;
    Bs[0][aseg * 4 + 1][arow] = bv.y;
    Bs[0][aseg * 4 + 2][arow] = bv.z;
    Bs[0][aseg * 4 + 3][arow] = bv.w;
    __syncthreads();

    float acc[4][4] = {};
    int buf = 0;
    for (int k0 = 0; k0 < 512; k0 += 16) {
        const bool more = (k0 + 16) < 512;
        if (more) {
            av = *(const float4*)(Aptr + k0 + 16);
            bv = *(const float4*)(Bptr + k0 + 16);
        }
#pragma unroll
        for (int kk = 0; kk < 16; kk++) {
            float a[4], b[4];
#pragma unroll
            for (int i2 = 0; i2 < 4; i2++) a[i2] = As[buf][kk][ty * 4 + i2];
#pragma unroll
            for (int j2 = 0; j2 < 4; j2++) b[j2] = Bs[buf][kk][tx * 4 + j2];
#pragma unroll
            for (int i2 = 0; i2 < 4; i2++)
#pragma unroll
                for (int j2 = 0; j2 < 4; j2++) acc[i2][j2] += a[i2] * b[j2];
        }
        if (more) {
            As[buf ^ 1][aseg * 4 + 0][arow] = av.x;
            As[buf ^ 1][aseg * 4 + 1][arow] = av.y;
            As[buf ^ 1][aseg * 4 + 2][arow] = av.z;
            As[buf ^ 1][aseg * 4 + 3][arow] = av.w;
            Bs[buf ^ 1][aseg * 4 + 0][arow] = bv.x;
            Bs[buf ^ 1][aseg * 4 + 1][arow] = bv.y;
            Bs[buf ^ 1][aseg * 4 + 2][arow] = bv.z;
            Bs[buf ^ 1][aseg * 4 + 3][arow] = bv.w;
        }
        __syncthreads();
        buf ^= 1;
    }
#pragma unroll
    for (int i2 = 0; i2 < 4; i2++) {
        const int i = m0 + ty * 4 + i2;
        const float si = stat[i], s2i = stat[256 + i];
#pragma unroll
        for (int j2 = 0; j2 < 4; j2++) {
            const int j = n0 + tx * 4 + j2;
            const float mean = (si + stat[512 + j]) * (1.f / 512.f);
            const float e2 = (s2i + 2.f * acc[i2][j2] + stat[768 + j]) * (1.f / 512.f);
            mrM[i * 256 + j] = mean;
            mrR[i * 256 + j] = rsqrtf(e2 - mean * mean + 1e-5f);
        }
    }
}

// ---------------- batched weight fragize: up to 8 jobs in one launch -------------
struct FragJobs {
    const float* src[8];
    float* dst[8];
    int ldb[8];
    int ntiles[8];
    int start[9];
};
__global__ void __launch_bounds__(256) fragize_all(FragJobs jb)
{
    int job = 0;
#pragma unroll
    for (int u = 1; u < 8; u++) if ((int)blockIdx.x >= jb.start[u]) job = u;
    const float* B = jb.src[job];
    float* F = jb.dst[job];
    const int ldb = jb.ldb[job], ntiles = jb.ntiles[job];
    const int g = (blockIdx.x - jb.start[job]) * 256 + threadIdx.x;
    const int lane = g & 31;
    const int pair = g >> 5;
    const int nt = pair % ntiles;
    const int t = pair / ntiles;
    const int gid = lane >> 2, tig = lane & 3;
    F[(long)g * 2 + 0] = tf32r(B[(long)(t * 8 + tig) * ldb + nt * 8 + gid]);
    F[(long)g * 2 + 1] = tf32r(B[(long)(t * 8 + tig + 4) * ldb + nt * 8 + gid]);
}

// ------ generic tf32 MMA GEMM: 64x64 CTA tile (more CTAs, less per-CTA MMA) ------
__global__ void __launch_bounds__(128) mma_gemm(
    const float* __restrict__ A, int lda, long sAz,
    const float* __restrict__ Bf, long sBz, int ntilesTotal,
    float* __restrict__ C, int ldc, long sCz, int K,
    const float* __restrict__ bias, int biasZmask)
{
    __shared__ float As[64][36];
    __shared__ float Bs[4][8][64];
    const int z = blockIdx.z;
    A += (long)z * sAz; Bf += (long)z * sBz; C += (long)z * sCz;
    const int m0 = blockIdx.y * 64, n0 = blockIdx.x * 64;
    const int ntile0 = blockIdx.x * 8;
    const int tid = threadIdx.x;
    const int warp = tid >> 5, lane = tid & 31;
    const int gid = lane >> 2, tig = lane & 3;

    float4 aR[4], bR[4];
#pragma unroll
    for (int it = 0; it < 4; it++) {
        const int idx = it * 128 + tid, row = idx >> 3, seg = idx & 7;
        aR[it] = *(const float4*)(A + (long)(m0 + row) * lda + seg * 4);
    }
#pragma unroll
    for (int it = 0; it < 4; it++) {
        const int idx = it * 128 + tid, ks = idx >> 7, rem = idx & 127;
        const int nt = rem >> 4, f4 = rem & 15;
        bR[it] = *(const float4*)(Bf + (long)ks * ntilesTotal * 64 + (long)(ntile0 + nt) * 64 + f4 * 4);
    }

    float acc[8][4] = {};
    for (int k0 = 0; k0 < K; k0 += 32) {
#pragma unroll
        for (int it = 0; it < 4; it++) {
            const int idx = it * 128 + tid, row = idx >> 3, seg = idx & 7;
            float4 w;
            w.x = tf32r(aR[it].x); w.y = tf32r(aR[it].y);
            w.z = tf32r(aR[it].z); w.w = tf32r(aR[it].w);
            *(float4*)&As[row][seg * 4] = w;
        }
#pragma unroll
        for (int it = 0; it < 4; it++) {
            const int idx = it * 128 + tid, ks = idx >> 7, rem = idx & 127;
            const int nt = rem >> 4, f4 = rem & 15;
            *(float4*)&Bs[ks][nt][f4 * 4] = bR[it];
        }
        __syncthreads();
        if (k0 + 32 < K) {
#pragma unroll
            for (int it = 0; it < 4; it++) {
                const int idx = it * 128 + tid, row = idx >> 3, seg = idx & 7;
                aR[it] = *(const float4*)(A + (long)(m0 + row) * lda + k0 + 32 + seg * 4);
            }
#pragma unroll
            for (int it = 0; it < 4; it++) {
                const int idx = it * 128 + tid, ks = idx >> 7, rem = idx & 127;
                const int nt = rem >> 4, f4 = rem & 15;
                bR[it] = *(const float4*)(Bf + (long)((k0 + 32) / 8 + ks) * ntilesTotal * 64
                                          + (long)(ntile0 + nt) * 64 + f4 * 4);
            }
        }
#pragma unroll
        for (int ks = 0; ks < 4; ks++) {
            const int kc = ks * 8;
            const unsigned a0 = __float_as_uint(As[warp * 16 + gid][kc + tig]);
            const unsigned a1 = __float_as_uint(As[warp * 16 + gid + 8][kc + tig]);
            const unsigned a2 = __float_as_uint(As[warp * 16 + gid][kc + tig + 4]);
            const unsigned a3 = __float_as_uint(As[warp * 16 + gid + 8][kc + tig + 4]);
#pragma unroll
            for (int ntl = 0; ntl < 8; ntl++) {
                const float2 b = *(const float2*)&Bs[ks][ntl][lane * 2];
                mma_tf32(acc[ntl], a0, a1, a2, a3, __float_as_uint(b.x), __float_as_uint(b.y));
            }
        }
        __syncthreads();
    }
    const int row = m0 + warp * 16 + gid;
    const bool addb = bias && ((biasZmask >> z) & 1);
#pragma unroll
    for (int ntl = 0; ntl < 8; ntl++) {
        const int col = n0 + ntl * 8 + tig * 2;
        float b0 = 0.f, b1 = 0.f;
        if (addb) { b0 = bias[col]; b1 = bias[col + 1]; }
        *(float2*)(C + (long)row * ldc + col) = make_float2(acc[ntl][0] + b0, acc[ntl][1] + b1);
        *(float2*)(C + (long)(row + 8) * ldc + col) = make_float2(acc[ntl][2] + b0, acc[ntl][3] + b1);
    }
}

// ---------------- transpose: Qt[k][n] from Q[n][k] ----------------
__global__ void __launch_bounds__(256) transpose_kernel(
    const float* __restrict__ Q, float* __restrict__ T)
{
    __shared__ float t[32][33];
    const int bk = blockIdx.x * 32;
    const int bn = blockIdx.y * 32;
    const int tx = threadIdx.x & 31, ty = threadIdx.x >> 5;
#pragma unroll
    for (int r = 0; r < 32; r += 8)
        t[ty + r][tx] = Q[(long)(bn + ty + r) * 512 + bk + tx];
    __syncthreads();
#pragma unroll
    for (int r = 0; r < 32; r += 8)
        T[(long)(bk + ty + r) * 256 + bn + tx] = t[tx][ty + r];
}

// ------- per-row sum / sumsq over TWO matrices (one pair-MLP half) ---------------
__global__ void __launch_bounds__(256) rowstats2_kernel(
    const float* __restrict__ src, float* __restrict__ stat)
{
    const int w = blockIdx.x * 8 + (threadIdx.x >> 5);  // 0..511
    const int lane = threadIdx.x & 31;
    const int mat = w >> 8, row = w & 255;
    const float* p = src + mat * 131072 + row * 512;
    float s = 0.f, s2 = 0.f;
#pragma unroll 4
    for (int k = lane; k < 512; k += 32) { const float v = p[k]; s += v; s2 += v * v; }
    s = warpSum(s); s2 = warpSum(s2);
    if (lane == 0) { stat[mat * 512 + row] = s; stat[mat * 512 + 256 + row] = s2; }
}

// ------- per-pair LN mean / rstd for the ep pair-MLP (bit-stable) ---------------
__global__ void __launch_bounds__(256) meanrstd_half(
    const float* __restrict__ stat, const float* __restrict__ dots,
    float* __restrict__ mrM, float* __restrict__ mrR)
{
    const int i = blockIdx.x, j = threadIdx.x;
    const int idx = i * 256 + j;
    const float m = (stat[i] + stat[512 + j]) * (1.f / 512.f);
    const float e2 = (stat[256 + i] + 2.f * dots[idx] + stat[768 + j]) * (1.f / 512.f);
    mrM[idx] = m;
    mrR[idx] = rsqrtf(e2 - m * m + 1e-5f);
}

// ---------------- edge predictor: 2 dst rows per CTA (fp32) ----------------
__global__ void __launch_bounds__(256) ep2_kernel(
    const float* __restrict__ P, const float* __restrict__ Qt,
    const float* __restrict__ mr,
    const float* __restrict__ gg, const float* __restrict__ bb,
    const float* __restrict__ w2, const float* __restrict__ b2,
    float* __restrict__ outActive, float* __restrict__ adj)
{
    const int i0 = blockIdx.x * 2;
    const int j = threadIdx.x;
    __shared__ float Pi[2][512], gs[512], bs[512], ws[512];
    for (int t = j; t < 512; t += 256) {
        Pi[0][t] = P[(long)i0 * 512 + t];
        Pi[1][t] = P[(long)(i0 + 1) * 512 + t];
        gs[t] = gg[t]; bs[t] = bb[t]; ws[t] = w2[t];
    }
    __syncthreads();
    const float m0 = mr[i0 * 256 + j],       r0 = mr[65536 + i0 * 256 + j];
    const float m1 = mr[(i0 + 1) * 256 + j], r1 = mr[65536 + (i0 + 1) * 256 + j];
    float acc0 = 0.f, acc1 = 0.f;
    for (int k = 0; k < 512; k += 4) {
        const float4 g4 = *(const float4*)&gs[k];
        const float4 b4 = *(const float4*)&bs[k];
        const float4 w4 = *(const float4*)&ws[k];
        const float4 p0 = *(const float4*)&Pi[0][k];
        const float4 p1 = *(const float4*)&Pi[1][k];
        const float q0 = Qt[(k + 0) * 256 + j];
        const float q1 = Qt[(k + 1) * 256 + j];
        const float q2 = Qt[(k + 2) * 256 + j];
        const float q3 = Qt[(k + 3) * 256 + j];
        acc0 += lrelu((p0.x + q0 - m0) * r0 * g4.x + b4.x) * w4.x;
        acc0 += lrelu((p0.y + q1 - m0) * r0 * g4.y + b4.y) * w4.y;
        acc0 += lrelu((p0.z + q2 - m0) * r0 * g4.z + b4.z) * w4.z;
        acc0 += lrelu((p0.w + q3 - m0) * r0 * g4.w + b4.w) * w4.w;
        acc1 += lrelu((p1.x + q0 - m1) * r1 * g4.x + b4.x) * w4.x;
        acc1 += lrelu((p1.y + q1 - m1) * r1 * g4.y + b4.y) * w4.y;
        acc1 += lrelu((p1.z + q2 - m1) * r1 * g4.z + b4.z) * w4.z;
        acc1 += lrelu((p1.w + q3 - m1) * r1 * g4.w + b4.w) * w4.w;
    }
    const float b2v = b2[0];
#pragma unroll
    for (int u = 0; u < 2; u++) {
        const int i = i0 + u;
        const float lg = (u ? acc1 : acc0) + b2v;
        const bool act = (lg > 0.f) && (i != j);
        outActive[i * 256 + j] = act ? 1.f : 0.f;
        adj[j * 256 + i] = (i == j) ? 1.f : (act ? 1.f : 0.f);
    }
}

// --------- fused edge-feature MMA kernel, register double-buffered (lean) --------
__global__ void __launch_bounds__(128) ef_mma_kernel(
    const float* __restrict__ RS, const float* __restrict__ mr,
    const float* __restrict__ gg, const float* __restrict__ bb,
    const float* __restrict__ w2f, const float* __restrict__ b2,
    float* __restrict__ outEF)
{
    const float* S = RS + 131072;
    const int i = blockIdx.y;
    const int j0 = blockIdx.x * 64;
    const int tid = threadIdx.x;
    __shared__ float Ri[512], gs[512], bs[512];
    __shared__ float Hs[64][36];
    __shared__ float Bs[4][16][64];
    __shared__ float mean_s[64], rstd_s[64];
    for (int t = tid; t < 512; t += 128) {
        Ri[t] = RS[i * 512 + t]; gs[t] = gg[t]; bs[t] = bb[t];
    }
    if (tid < 64) {
        mean_s[tid] = mr[131072 + i * 256 + j0 + tid];
        rstd_s[tid] = mr[196608 + i * 256 + j0 + tid];
    }
    const int warp = tid >> 5, lane = tid & 31;
    const int gid = lane >> 2, tig = lane & 3;

    float4 sR[4], wR[8];
#pragma unroll
    for (int it = 0; it < 4; it++) {
        const int idx = it * 128 + tid, row = idx >> 3, seg = idx & 7;
        sR[it] = *(const float4*)(S + (long)(j0 + row) * 512 + seg * 4);
    }
#pragma unroll
    for (int it = 0; it < 8; it++) {
        const int idx = it * 128 + tid, ks = idx >> 8, rem = idx & 255;
        const int nt = rem >> 4, f4 = rem & 15;
        wR[it] = *(const float4*)(w2f + (long)ks * 1024 + nt * 64 + f4 * 4);
    }
    __syncthreads();

    float acc[16][4] = {};
    for (int k0 = 0; k0 < 512; k0 += 32) {
#pragma unroll
        for (int it = 0; it < 4; it++) {
            const int idx = it * 128 + tid, row = idx >> 3, seg = idx & 7;
            const int k = k0 + seg * 4;
            const float4 r4 = *(const float4*)&Ri[k];
            const float4 g4 = *(const float4*)&gs[k];
            const float4 b4 = *(const float4*)&bs[k];
            const float m = mean_s[row], rs = rstd_s[row];
            float4 h;
            h.x = tf32r(lrelu((r4.x + sR[it].x - m) * rs * g4.x + b4.x));
            h.y = tf32r(lrelu((r4.y + sR[it].y - m) * rs * g4.y + b4.y));
            h.z = tf32r(lrelu((r4.z + sR[it].z - m) * rs * g4.z + b4.z));
            h.w = tf32r(lrelu((r4.w + sR[it].w - m) * rs * g4.w + b4.w));
            *(float4*)&Hs[row][seg * 4] = h;
        }
#pragma unroll
        for (int it = 0; it < 8; it++) {
            const int idx = it * 128 + tid, ks = idx >> 8, rem = idx & 255;
            const int nt = rem >> 4, f4 = rem & 15;
            *(float4*)&Bs[ks][nt][f4 * 4] = wR[it];
        }
        __syncthreads();
        if (k0 + 32 < 512) {
#pragma unroll
            for (int it = 0; it < 4; it++) {
                const int idx = it * 128 + tid, row = idx >> 3, seg = idx & 7;
                sR[it] = *(const float4*)(S + (long)(j0 + row) * 512 + k0 + 32 + seg * 4);
            }
#pragma unroll
            for (int it = 0; it < 8; it++) {
                const int idx = it * 128 + tid, ks = idx >> 8, rem = idx & 255;
                const int nt = rem >> 4, f4 = rem & 15;
                wR[it] = *(const float4*)(w2f + (long)((k0 + 32) / 8 + ks) * 1024 + nt * 64 + f4 * 4);
            }
        }
#pragma unroll
        for (int ks = 0; ks < 4; ks++) {
            const int kc = ks * 8;
            const unsigned a0 = __float_as_uint(Hs[warp * 16 + gid][kc + tig]);
            const unsigned a1 = __float_as_uint(Hs[warp * 16 + gid + 8][kc + tig]);
            const unsigned a2 = __float_as_uint(Hs[warp * 16 + gid][kc + tig + 4]);
            const unsigned a3 = __float_as_uint(Hs[warp * 16 + gid + 8][kc + tig + 4]);
#pragma unroll
            for (int nt = 0; nt < 16; nt++) {
                const float2 b = *(const float2*)&Bs[ks][nt][lane * 2];
                mma_tf32(acc[nt], a0, a1, a2, a3, __float_as_uint(b.x), __float_as_uint(b.y));
            }
        }
        __syncthreads();
    }
    const int row = j0 + warp * 16 + gid;
#pragma unroll
    for (int nt = 0; nt < 16; nt++) {
        const int col = nt * 8 + tig * 2;
        const float b0 = b2[col], b1 = b2[col + 1];
        float* dst = outEF + ((long)i * 256 + row) * 128 + col;
        *(float2*)dst = make_float2(acc[nt][0] + b0, acc[nt][1] + b1);
        *(float2*)(dst + 8 * 128) = make_float2(acc[nt][2] + b0, acc[nt][3] + b1);
    }
}

// ---- GAT s-GEMM: 64x64 tiles (128 CTAs), frag stores + a_src/a_dst partials -----
__global__ void __launch_bounds__(128) gat_s_mma(
    const float* __restrict__ A,
    const float* __restrict__ Bf,
    const float* __restrict__ a_src, const float* __restrict__ a_dst,
    float* __restrict__ Sf,
    float* __restrict__ asdp)    // [2][256][4][8]
{
    __shared__ float As[64][36];
    __shared__ float Bs[4][8][64];
    const int m0 = blockIdx.y * 64;
    const int ntile0 = blockIdx.x * 8;
    const int head = blockIdx.x >> 3;
    const int xo = blockIdx.x & 7;
    const int nh0 = xo * 64;
    const int tid = threadIdx.x;
    const int warp = tid >> 5, lane = tid & 31;
    const int gid = lane >> 2, tig = lane & 3;

    float4 aR[4], bR[4];
#pragma unroll
    for (int it = 0; it < 4; it++) {
        const int idx = it * 128 + tid, row = idx >> 3, seg = idx & 7;
        aR[it] = *(const float4*)(A + (long)(m0 + row) * 512 + seg * 4);
    }
#pragma unroll
    for (int it = 0; it < 4; it++) {
        const int idx = it * 128 + tid, ks = idx >> 7, rem = idx & 127;
        const int nt = rem >> 4, f4 = rem & 15;
        bR[it] = *(const float4*)(Bf + (long)ks * 256 * 64 + (long)(ntile0 + nt) * 64 + f4 * 4);
    }

    float acc[8][4] = {};
    for (int k0 = 0; k0 < 512; k0 += 32) {
#pragma unroll
        for (int it = 0; it < 4; it++) {
            const int idx = it * 128 + tid, row = idx >> 3, seg = idx & 7;
            float4 w;
            w.x = tf32r(aR[it].x); w.y = tf32r(aR[it].y);
            w.z = tf32r(aR[it].z); w.w = tf32r(aR[it].w);
            *(float4*)&As[row][seg * 4] = w;
        }
#pragma unroll
        for (int it = 0; it < 4; it++) {
            const int idx = it * 128 + tid, ks = idx >> 7, rem = idx & 127;
            const int nt = rem >> 4, f4 = rem & 15;
            *(float4*)&Bs[ks][nt][f4 * 4] = bR[it];
        }
        __syncthreads();
        if (k0 + 32 < 512) {
#pragma unroll
            for (int it = 0; it < 4; it++) {
                const int idx = it * 128 + tid, row = idx >> 3, seg = idx & 7;
                aR[it] = *(const float4*)(A + (long)(m0 + row) * 512 + k0 + 32 + seg * 4);
            }
#pragma unroll
            for (int it = 0; it < 4; it++) {
                const int idx = it * 128 + tid, ks = idx >> 7, rem = idx & 127;
                const int nt = rem >> 4, f4 = rem & 15;
                bR[it] = *(const float4*)(Bf + (long)((k0 + 32) / 8 + ks) * 256 * 64
                                          + (long)(ntile0 + nt) * 64 + f4 * 4);
            }
        }
#pragma unroll
        for (int ks = 0; ks < 4; ks++) {
            const int kc = ks * 8;
            const unsigned a0 = __float_as_uint(As[warp * 16 + gid][kc + tig]);
            const unsigned a1 = __float_as_uint(As[warp * 16 + gid + 8][kc + tig]);
            const unsigned a2 = __float_as_uint(As[warp * 16 + gid][kc + tig + 4]);
            const unsigned a3 = __float_as_uint(As[warp * 16 + gid + 8][kc + tig + 4]);
#pragma unroll
            for (int ntl = 0; ntl < 8; ntl++) {
                const float2 b = *(const float2*)&Bs[ks][ntl][lane * 2];
                mma_tf32(acc[ntl], a0, a1, a2, a3, __float_as_uint(b.x), __float_as_uint(b.y));
            }
        }
        __syncthreads();
    }
    // epilogue: frag-layout stores + partial dots (deterministic, 8 slices)
    const int row = m0 + warp * 16 + gid;
    const int r1 = row + 8;
    const int t0 = row >> 3, kk0 = row & 7;
    const int t1 = r1 >> 3, kk1 = r1 & 7;
    float* SfH = Sf + head * 131072;
    const float* asr = a_src + head * 512;
    const float* adr = a_dst + head * 512;
    float ds0 = 0.f, dd0 = 0.f, ds1 = 0.f, dd1 = 0.f;
#pragma unroll
    for (int ntl = 0; ntl < 8; ntl++) {
        const int c0 = nh0 + ntl * 8 + tig * 2;
#pragma unroll
        for (int u = 0; u < 2; u++) {
            const int ch = c0 + u;
            const float asv = asr[ch], adv = adr[ch];
            const float v0 = acc[ntl][u];
            const float v1 = acc[ntl][2 + u];
            ds0 += v0 * asv; dd0 += v0 * adv;
            ds1 += v1 * asv; dd1 += v1 * adv;
            const int ntf = ch >> 3, gidf = ch & 7;
            SfH[((t0 * 64 + ntf) * 32 + gidf * 4 + (kk0 & 3)) * 2 + (kk0 >> 2)] = tf32r(v0);
            SfH[((t1 * 64 + ntf) * 32 + gidf * 4 + (kk1 & 3)) * 2 + (kk1 >> 2)] = tf32r(v1);
        }
    }
    ds0 += __shfl_xor_sync(FULLMASK, ds0, 1); ds0 += __shfl_xor_sync(FULLMASK, ds0, 2);
    dd0 += __shfl_xor_sync(FULLMASK, dd0, 1); dd0 += __shfl_xor_sync(FULLMASK, dd0, 2);
    ds1 += __shfl_xor_sync(FULLMASK, ds1, 1); ds1 += __shfl_xor_sync(FULLMASK, ds1, 2);
    dd1 += __shfl_xor_sync(FULLMASK, dd1, 1); dd1 += __shfl_xor_sync(FULLMASK, dd1, 2);
    if (tig == 0) {
        asdp[(row * 4 + head) * 8 + xo] = ds0;
        asdp[8192 + (row * 4 + head) * 8 + xo] = dd0;
        asdp[(r1 * 4 + head) * 8 + xo] = ds1;
        asdp[8192 + (r1 * 4 + head) * 8 + xo] = dd1;
    }
}

// --------- attention stats: sum 8 partials, per-(i,head) max and 1/Z ------------
__global__ void __launch_bounds__(256) attn_stats_kernel(
    const float* __restrict__ asdp, const float* __restrict__ adj,
    float* __restrict__ asd, float* __restrict__ stats)
{
    __shared__ float sm[8];
    __shared__ float adi[4];
    const int i = blockIdx.x, j = threadIdx.x;
    const int warp = j >> 5, lane = j & 31;
    float asv[4];
#pragma unroll
    for (int h = 0; h < 4; h++) {
        const int b = (j * 4 + h) * 8;
        float s = 0.f, d = 0.f;
#pragma unroll
        for (int u = 0; u < 8; u++) { s += asdp[b + u]; d += asdp[8192 + b + u]; }
        asv[h] = s;
        asd[j * 4 + h] = s;
        asd[1024 + j * 4 + h] = d;
        if (j == i) adi[h] = d;
    }
    __syncthreads();
    const bool on = adj[i * 256 + j] > 0.5f;
#pragma unroll
    for (int h = 0; h < 4; h++) {
        const float lg = lrelu(adi[h] + asv[h]);
        float v = on ? lg : -1e30f;
        v = warpMax(v);
        if (lane == 0) sm[warp] = v;
        __syncthreads();
        const float m = fmaxf(fmaxf(fmaxf(sm[0], sm[1]), fmaxf(sm[2], sm[3])),
                              fmaxf(fmaxf(sm[4], sm[5]), fmaxf(sm[6], sm[7])));
        __syncthreads();
        const float w = on ? __expf(lg - m) : 0.f;
        float ws = warpSum(w);
        if (lane == 0) sm[warp] = ws;
        __syncthreads();
        const float Z = sm[0] + sm[1] + sm[2] + sm[3] + sm[4] + sm[5] + sm[6] + sm[7];
        __syncthreads();
        if (j == 0) { stats[i * 8 + h * 2] = m; stats[i * 8 + h * 2 + 1] = 1.f / Z; }
    }
}

// ---- fused aggregation: 64x64 tiles (128 CTAs), alpha computed on the fly -------
__global__ void __launch_bounds__(128) agg_mma(
    const float* __restrict__ adj, const float* __restrict__ asd,
    const float* __restrict__ stats, const float* __restrict__ Sf,
    float* __restrict__ agg)
{
    __shared__ float As[64][36];
    __shared__ float Bs[4][8][64];
    __shared__ float m_s[64], iz_s[64], ad_s[64];
    const int head = blockIdx.z;
    const int i0 = blockIdx.y * 64;
    const int n0 = blockIdx.x * 64;
    const int ntile0 = blockIdx.x * 8;
    const int tid = threadIdx.x;
    const int warp = tid >> 5, lane = tid & 31;
    const int gid = lane >> 2, tig = lane & 3;
    const float* Bfh = Sf + head * 131072;

    if (tid < 64) {
        const int r = i0 + tid;
        m_s[tid] = stats[r * 8 + head * 2];
        iz_s[tid] = stats[r * 8 + head * 2 + 1];
        ad_s[tid] = asd[1024 + r * 4 + head];
    }

    float4 jR[4], bR[4];
#pragma unroll
    for (int it = 0; it < 4; it++) {
        const int idx = it * 128 + tid, row = idx >> 3, seg = idx & 7;
        jR[it] = *(const float4*)(adj + (long)(i0 + row) * 256 + seg * 4);
    }
#pragma unroll
    for (int it = 0; it < 4; it++) {
        const int idx = it * 128 + tid, ks = idx >> 7, rem = idx & 127;
        const int nt = rem >> 4, f4 = rem & 15;
        bR[it] = *(const float4*)(Bfh + (long)ks * 64 * 64 + (long)(ntile0 + nt) * 64 + f4 * 4);
    }
    __syncthreads();

    float acc[8][4] = {};
    for (int k0 = 0; k0 < 256; k0 += 32) {
#pragma unroll
        for (int it = 0; it < 4; it++) {
            const int idx = it * 128 + tid, row = idx >> 3, seg = idx & 7;
            float av[4];
            *(float4*)av = jR[it];
            const float adv = ad_s[row], mm = m_s[row], iz = iz_s[row];
#pragma unroll
            for (int u = 0; u < 4; u++) {
                const int jj = k0 + seg * 4 + u;
                const float lg = lrelu(adv + asd[jj * 4 + head]);
                const float val = (av[u] > 0.5f) ? __expf(lg - mm) * iz : 0.f;
                As[row][seg * 4 + u] = tf32r(val);
            }
        }
#pragma unroll
        for (int it = 0; it < 4; it++) {
            const int idx = it * 128 + tid, ks = idx >> 7, rem = idx & 127;
            const int nt = rem >> 4, f4 = rem & 15;
            *(float4*)&Bs[ks][nt][f4 * 4] = bR[it];
        }
        __syncthreads();
        if (k0 + 32 < 256) {
#pragma unroll
            for (int it = 0; it < 4; it++) {
                const int idx = it * 128 + tid, row = idx >> 3, seg = idx & 7;
                jR[it] = *(const float4*)(adj + (long)(i0 + row) * 256 + k0 + 32 + seg * 4);
            }
#pragma unroll
            for (int it = 0; it < 4; it++) {
                const int idx = it * 128 + tid, ks = idx >> 7, rem = idx & 127;
                const int nt = rem >> 4, f4 = rem & 15;
                bR[it] = *(const float4*)(Bfh + (long)((k0 + 32) / 8 + ks) * 64 * 64
                                          + (long)(ntile0 + nt) * 64 + f4 * 4);
            }
        }
#pragma unroll
        for (int ks = 0; ks < 4; ks++) {
            const int kc = ks * 8;
            const unsigned a0 = __float_as_uint(As[warp * 16 + gid][kc + tig]);
            const unsigned a1 = __float_as_uint(As[warp * 16 + gid + 8][kc + tig]);
            const unsigned a2 = __float_as_uint(As[warp * 16 + gid][kc + tig + 4]);
            const unsigned a3 = __float_as_uint(As[warp * 16 + gid + 8][kc + tig + 4]);
#pragma unroll
            for (int ntl = 0; ntl < 8; ntl++) {
                const float2 b = *(const float2*)&Bs[ks][ntl][lane * 2];
                mma_tf32(acc[ntl], a0, a1, a2, a3, __float_as_uint(b.x), __float_as_uint(b.y));
            }
        }
        __syncthreads();
    }
    const int row = i0 + warp * 16 + gid;
#pragma unroll
    for (int ntl = 0; ntl < 8; ntl++) {
        const int col = head * 512 + n0 + ntl * 8 + tig * 2;
        *(float2*)(agg + (long)row * 2048 + col) = make_float2(acc[ntl][0], acc[ntl][1]);
        *(float2*)(agg + (long)(row + 8) * 2048 + col) = make_float2(acc[ntl][2], acc[ntl][3]);
    }
}

// ---------------- mean over heads + bias + LeakyReLU ----------------
__global__ void __launch_bounds__(256) combine_kernel(
    const float* __restrict__ agg, const float* __restrict__ gb, float* __restrict__ x)
{
    const int i = blockIdx.x;
    for (int c = threadIdx.x; c < 512; c += 256) {
        const long b = (long)i * 2048;
        const float v = 0.25f * (agg[b + c] + agg[b + 512 + c] + agg[b + 1024 + c] + agg[b + 1536 + c]) + gb[c];
        x[i * 512 + c] = lrelu(v);
    }
}

// ---------------- row LayerNorm + LeakyReLU ----------------
__global__ void __launch_bounds__(256) ln_lrelu_kernel(
    float* __restrict__ h, const float* __restrict__ gg, const float* __restrict__ bb)
{
    __shared__ float sm[8];
    const int i = blockIdx.x;
    const int t = threadIdx.x;
    const int warp = t >> 5, lane = t & 31;
    float* row = h + (long)i * 512;
    const float v0 = row[t], v1 = row[t + 256];
    float s = warpSum(v0 + v1);
    if (lane == 0) sm[warp] = s;
    __syncthreads();
    const float mean = (sm[0] + sm[1] + sm[2] + sm[3] + sm[4] + sm[5] + sm[6] + sm[7]) * (1.f / 512.f);
    __syncthreads();
    const float d0 = v0 - mean, d1 = v1 - mean;
    float s2 = warpSum(d0 * d0 + d1 * d1);
    if (lane == 0) sm[warp] = s2;
    __syncthreads();
    const float var = (sm[0] + sm[1] + sm[2] + sm[3] + sm[4] + sm[5] + sm[6] + sm[7]) * (1.f / 512.f);
    const float rstd = rsqrtf(var + 1e-5f);
    row[t] = lrelu(d0 * rstd * gg[t] + bb[t]);
    row[t + 256] = lrelu(d1 * rstd * gg[t + 256] + bb[t + 256]);
}

// ===================================================================================
extern "C" void kernel_launch(void* const* d_in, const int* in_sizes, int n_in,
                              void* d_out, int out_size)
{
    (void)in_sizes; (void)n_in; (void)out_size;
    const float* emb     = (const float*)d_in[0];
    const float* ep_w1   = (const float*)d_in[1];
    const float* ep_b1   = (const float*)d_in[2];
    const float* ep_g    = (const float*)d_in[3];
    const float* ep_beta = (const float*)d_in[4];
    const float* ep_w2   = (const float*)d_in[5];
    const float* ep_b2   = (const float*)d_in[6];
    const float* ef_w1   = (const float*)d_in[7];
    const float* ef_b1   = (const float*)d_in[8];
    const float* ef_g    = (const float*)d_in[9];
    const float* ef_beta = (const float*)d_in[10];
    const float* ef_w2   = (const float*)d_in[11];
    const float* ef_b2   = (const float*)d_in[12];
    const float* gat_W   = (const float*)d_in[13];
    const float* gat_as  = (const float*)d_in[14];
    const float* gat_ad  = (const float*)d_in[15];
    const float* gat_b   = (const float*)d_in[16];
    const float* op_w1   = (const float*)d_in[17];
    const float* op_b1   = (const float*)d_in[18];
    const float* op_g    = (const float*)d_in[19];
    const float* op_beta = (const float*)d_in[20];
    const float* op_w2   = (const float*)d_in[21];
    const float* op_b2   = (const float*)d_in[22];

    float *pPQ, *pRS, *pStat, *pT, *pDot, *pMr, *pAdj, *pAsdP, *pAsd, *pStats,
          *pAgg, *pX, *pH, *pW2f, *pW1f, *pWf, *pSf, *pOpf;
    cudaGetSymbolAddress((void**)&pPQ, g_PQ);
    cudaGetSymbolAddress((void**)&pRS, g_RS);
    cudaGetSymbolAddress((void**)&pStat, g_stat);
    cudaGetSymbolAddress((void**)&pT, g_t);
    cudaGetSymbolAddress((void**)&pDot, g_dot);
    cudaGetSymbolAddress((void**)&pMr, g_mr);
    cudaGetSymbolAddress((void**)&pAdj, g_adj);
    cudaGetSymbolAddress((void**)&pAsdP, g_asdp);
    cudaGetSymbolAddress((void**)&pAsd, g_asd);
    cudaGetSymbolAddress((void**)&pStats, g_stats);
    cudaGetSymbolAddress((void**)&pAgg, g_agg);
    cudaGetSymbolAddress((void**)&pX, g_x);
    cudaGetSymbolAddress((void**)&pH, g_h);
    cudaGetSymbolAddress((void**)&pW2f, g_w2frag);
    cudaGetSymbolAddress((void**)&pW1f, g_w1frag);
    cudaGetSymbolAddress((void**)&pWf, g_wfrag);
    cudaGetSymbolAddress((void**)&pSf, g_sfrag);
    cudaGetSymbolAddress((void**)&pOpf, g_opfrag);

    float* out0      = (float*)d_out;
    float* outActive = out0 + 256 * 512;
    float* outEF     = outActive + 256 * 256;

    static cudaStream_t s1 = nullptr, s2 = nullptr;
    static cudaEvent_t eOrigin = nullptr, eS0 = nullptr, eEF = nullptr;
    if (!s1) {
        int leastPrio = 0, greatestPrio = 0;
        cudaDeviceGetStreamPriorityRange(&leastPrio, &greatestPrio);
        cudaStreamCreateWithPriority(&s1, cudaStreamNonBlocking, leastPrio);
        cudaStreamCreateWithPriority(&s2, cudaStreamNonBlocking, leastPrio);
        cudaEventCreateWithFlags(&eOrigin, cudaEventDisableTiming);
        cudaEventCreateWithFlags(&eS0, cudaEventDisableTiming);
        cudaEventCreateWithFlags(&eEF, cudaEventDisableTiming);
    }

    cudaEventRecord(eOrigin, 0);
    cudaStreamWaitEvent(s1, eOrigin, 0);
    cudaStreamWaitEvent(s2, eOrigin, 0);

    const int BIG = 0x7fffffff;

    // ---- s1 (low prio): ef branch: fragA -> RS -> rowstats -> dotmr -> ef_mma ----
    FragJobs ja;
    ja.src[0] = ef_w1;             ja.dst[0] = pW1f;          ja.ldb[0] = 512; ja.ntiles[0] = 64;
    ja.src[1] = ef_w1 + 512 * 512; ja.dst[1] = pW1f + 262144; ja.ldb[1] = 512; ja.ntiles[1] = 64;
    ja.src[2] = ef_w2;             ja.dst[2] = pW2f;          ja.ldb[2] = 128; ja.ntiles[2] = 16;
    for (int u = 3; u < 8; u++) { ja.src[u] = ef_w2; ja.dst[u] = pW2f; ja.ldb[u] = 128; ja.ntiles[u] = 16; }
    ja.start[0] = 0; ja.start[1] = 512; ja.start[2] = 1024;
    for (int u = 3; u < 9; u++) ja.start[u] = BIG;
    fragize_all<<<1152, 256, 0, s1>>>(ja);
    mma_gemm<<<dim3(8, 4, 2), 128, 0, s1>>>(emb, 512, 0, pW1f, 262144, 64,
                                            pRS, 512, 131072, 512, ef_b1, 0b10);
    rowstats2_kernel<<<64, 256, 0, s1>>>(pRS, pStat + 1024);
    dotmr_kernel<<<dim3(4, 4), 256, 0, s1>>>(pRS, pRS + 131072, pStat + 1024,
                                             pMr + 131072, pMr + 196608);
    ef_mma_kernel<<<dim3(4, 256), 128, 0, s1>>>(pRS, pMr, ef_g, ef_beta, pW2f, ef_b2, outEF);
    cudaEventRecord(eEF, s1);

    // ---- s2 (low prio): GAT/op weight frags, then layer-0 gat_s_mma ----
    FragJobs jbb;
    jbb.src[0] = op_w1;                  jbb.dst[0] = pOpf;           jbb.ldb[0] = 512;  jbb.ntiles[0] = 64;
    jbb.src[1] = op_w2;                  jbb.dst[1] = pOpf + 262144;  jbb.ldb[1] = 512;  jbb.ntiles[1] = 64;
    jbb.src[2] = gat_W;                  jbb.dst[2] = pWf;            jbb.ldb[2] = 2048; jbb.ntiles[2] = 256;
    jbb.src[3] = gat_W + 512 * 2048;     jbb.dst[3] = pWf + 1048576;  jbb.ldb[3] = 2048; jbb.ntiles[3] = 256;
    jbb.src[4] = gat_W + 2 * 512 * 2048; jbb.dst[4] = pWf + 2097152;  jbb.ldb[4] = 2048; jbb.ntiles[4] = 256;
    for (int u = 5; u < 8; u++) { jbb.src[u] = op_w1; jbb.dst[u] = pOpf; jbb.ldb[u] = 512; jbb.ntiles[u] = 64; }
    jbb.start[0] = 0; jbb.start[1] = 512; jbb.start[2] = 1024; jbb.start[3] = 3072;
    jbb.start[4] = 5120;
    for (int u = 5; u < 9; u++) jbb.start[u] = BIG;
    fragize_all<<<7168, 256, 0, s2>>>(jbb);
    gat_s_mma<<<dim3(32, 4), 128, 0, s2>>>(emb, pWf, gat_as, gat_ad, pSf, pAsdP);
    cudaEventRecord(eS0, s2);

    // ---- main (default prio): complete ep branch (fp32, bit-stable) ----
    gemm_kernel<<<dim3(8, 4, 2), 256>>>(emb, 512, 0, ep_w1, 512, 512 * 512,
                                        pPQ, 512, 256 * 512, ep_b1, 0b10, 512);
    transpose_kernel<<<dim3(16, 8), 256>>>(pPQ + 131072, pT);
    gemm_kernel<<<dim3(4, 4, 1), 256>>>(pPQ, 512, 0, pT, 256, 0,
                                        pDot, 256, 0, nullptr, 0, 512);
    rowstats2_kernel<<<64, 256>>>(pPQ, pStat);
    meanrstd_half<<<256, 256>>>(pStat, pDot, pMr, pMr + 65536);
    ep2_kernel<<<128, 256>>>(pPQ, pT, pMr, ep_g, ep_beta, ep_w2, ep_b2, outActive, pAdj);

    // ---- main: GAT stack (layer-0 s-GEMM already done on s2) ----
    cudaStreamWaitEvent(0, eS0, 0);
    attn_stats_kernel<<<256, 256>>>(pAsdP, pAdj, pAsd, pStats);
    agg_mma<<<dim3(8, 4, 4), 128>>>(pAdj, pAsd, pStats, pSf, pAgg);
    combine_kernel<<<256, 256>>>(pAgg, gat_b, pX);
    for (int l = 1; l < 3; l++) {
        gat_s_mma<<<dim3(32, 4), 128>>>(pX, pWf + (long)l * 1048576,
                                        gat_as + l * 2048, gat_ad + l * 2048, pSf, pAsdP);
        attn_stats_kernel<<<256, 256>>>(pAsdP, pAdj, pAsd, pStats);
        agg_mma<<<dim3(8, 4, 4), 128>>>(pAdj, pAsd, pStats, pSf, pAgg);
        combine_kernel<<<256, 256>>>(pAgg, gat_b + l * 512, pX);
    }

    // ---- main: output projection ----
    mma_gemm<<<dim3(8, 4, 1), 128>>>(pX, 512, 0, pOpf, 0, 64, pH, 512, 0, 512, op_b1, 1);
    ln_lrelu_kernel<<<256, 256>>>(pH, op_g, op_beta);
    mma_gemm<<<dim3(8, 4, 1), 128>>>(pH, 512, 0, pOpf + 262144, 0, 64, out0, 512, 0, 512, op_b2, 1);

    // ---- join ef branch before returning ----
    cudaStreamWaitEvent(0, eEF, 0);
}

// round 17
// speedup vs baseline: 1.1410x; 1.1410x over previous
#include <cuda_runtime.h>

#define FULLMASK 0xffffffffu

static __device__ __forceinline__ float lrelu(float x) { return x > 0.f ? x : 0.2f * x; }

static __device__ __forceinline__ float warpSum(float v) {
#pragma unroll
    for (int o = 16; o; o >>= 1) v += __shfl_xor_sync(FULLMASK, v, o);
    return v;
}
static __device__ __forceinline__ float warpMax(float v) {
#pragma unroll
    for (int o = 16; o; o >>= 1) v = fmaxf(v, __shfl_xor_sync(FULLMASK, v, o));
    return v;
}

static __device__ __forceinline__ float tf32r(float x) {
    unsigned u;
    asm("cvt.rna.tf32.f32 %0, %1;" : "=r"(u) : "f"(x));
    return __uint_as_float(u);
}

static __device__ __forceinline__ void mma_tf32(float* acc,
    unsigned a0, unsigned a1, unsigned a2, unsigned a3, unsigned b0, unsigned b1)
{
    asm volatile(
        "mma.sync.aligned.m16n8k8.row.col.f32.tf32.tf32.f32 "
        "{%0,%1,%2,%3},{%4,%5,%6,%7},{%8,%9},{%0,%1,%2,%3};"
        : "+f"(acc[0]), "+f"(acc[1]), "+f"(acc[2]), "+f"(acc[3])
        : "r"(a0), "r"(a1), "r"(a2), "r"(a3), "r"(b0), "r"(b1));
}

// ---------------- scratch (device globals; no allocation allowed) ----------------
__device__ float g_PQ[2 * 256 * 512];     // P, Qb (fp32 — ep path stays fp32)
__device__ float g_RS[2 * 256 * 512];     // R, Sb
__device__ float g_stat[8 * 256];         // [0..1023]=ep stats, [1024..2047]=ef stats
__device__ float g_t[512 * 256];          // Qt
__device__ float g_dot[256 * 256];        // dotEP (fp32)
__device__ float g_mr[4 * 256 * 256];     // epMean, epRstd, efMean, efRstd
__device__ float g_adj[256 * 256];
__device__ float g_asdp[2 * 256 * 4 * 4]; // per-x-tile partial a_src/a_dst dots
__device__ float g_asd[2 * 256 * 4];      // summed a_src / a_dst per node
__device__ float g_stats[256 * 8];        // per (i,head): max, 1/Z
__device__ float g_agg[256 * 2048];
__device__ float g_x[256 * 512];
__device__ float g_h[256 * 512];
__device__ float g_w2frag[64 * 16 * 64];      // ef_w2 frags
__device__ float g_w1frag[2 * 64 * 64 * 64];  // ef_w1 frags
__device__ float g_wfrag[3 * 64 * 256 * 64];  // gat_W frags
__device__ float g_sfrag[4 * 32 * 64 * 64];   // s per-head frags
__device__ float g_opfrag[2 * 64 * 64 * 64];  // op_w1 / op_w2 frags

// ------------- fp32 FFMA GEMM, double-buffered (ep path: bit-stable k order) -----
__global__ void __launch_bounds__(256) gemm_kernel(
    const float* __restrict__ A, int lda, long sAz,
    const float* __restrict__ B, int ldb, long sBz,
    float* __restrict__ C, int ldc, long sCz,
    const float* __restrict__ bias, int biasZmask, int K)
{
    __shared__ float As[2][16][65];
    __shared__ float Bs[2][16][68];
    const int z = blockIdx.z;
    A += (long)z * sAz; B += (long)z * sBz; C += (long)z * sCz;
    const int m0 = blockIdx.y * 64, n0 = blockIdx.x * 64;
    const int tid = threadIdx.x;
    const int tx = tid & 15, ty = tid >> 4;
    const int arow = tid >> 2, aseg = tid & 3;
    const int brow = tid >> 4, bseg = tid & 15;
    const float* Aptr = A + (long)(m0 + arow) * lda + aseg * 4;
    const float* Bptr = B + (long)brow * ldb + n0 + bseg * 4;

    float4 av = *(const float4*)(Aptr);
    float4 bv = *(const float4*)(Bptr);
    As[0][aseg * 4 + 0][arow] = av.x;
    As[0][aseg * 4 + 1][arow] = av.y;
    As[0][aseg * 4 + 2][arow] = av.z;
    As[0][aseg * 4 + 3][arow] = av.w;
    *(float4*)&Bs[0][brow][bseg * 4] = bv;
    __syncthreads();

    float acc[4][4] = {};
    int buf = 0;
    for (int k0 = 0; k0 < K; k0 += 16) {
        const bool more = (k0 + 16) < K;
        if (more) {
            av = *(const float4*)(Aptr + k0 + 16);
            bv = *(const float4*)(Bptr + (long)(k0 + 16) * ldb);
        }
#pragma unroll
        for (int kk = 0; kk < 16; kk++) {
            float a[4], b[4];
#pragma unroll
            for (int i2 = 0; i2 < 4; i2++) a[i2] = As[buf][kk][ty * 4 + i2];
            const float4 b4 = *(const float4*)&Bs[buf][kk][tx * 4];
            b[0] = b4.x; b[1] = b4.y; b[2] = b4.z; b[3] = b4.w;
#pragma unroll
            for (int i2 = 0; i2 < 4; i2++)
#pragma unroll
                for (int j2 = 0; j2 < 4; j2++) acc[i2][j2] += a[i2] * b[j2];
        }
        if (more) {
            As[buf ^ 1][aseg * 4 + 0][arow] = av.x;
            As[buf ^ 1][aseg * 4 + 1][arow] = av.y;
            As[buf ^ 1][aseg * 4 + 2][arow] = av.z;
            As[buf ^ 1][aseg * 4 + 3][arow] = av.w;
            *(float4*)&Bs[buf ^ 1][brow][bseg * 4] = bv;
        }
        __syncthreads();
        buf ^= 1;
    }
    const bool addb = bias && ((biasZmask >> z) & 1);
    float4 bb = make_float4(0.f, 0.f, 0.f, 0.f);
    if (addb) bb = *(const float4*)(bias + n0 + tx * 4);
#pragma unroll
    for (int i2 = 0; i2 < 4; i2++) {
        const int m = m0 + ty * 4 + i2;
        float4 v = make_float4(acc[i2][0] + bb.x, acc[i2][1] + bb.y,
                               acc[i2][2] + bb.z, acc[i2][3] + bb.w);
        *(float4*)(C + (long)m * ldc + n0 + tx * 4) = v;
    }
}

// ------- fp32 dot(R_i,S_j) GEMM with transposed-B staging + fused mean/rstd ------
// 64x64 tile, double-buffered. Epilogue writes per-pair LN mean and rstd directly.
__global__ void __launch_bounds__(256) dotmr_kernel(
    const float* __restrict__ R, const float* __restrict__ S,
    const float* __restrict__ stat,
    float* __restrict__ mrM, float* __restrict__ mrR)
{
    __shared__ float As[2][16][65];
    __shared__ float Bs[2][16][65];
    const int m0 = blockIdx.y * 64, n0 = blockIdx.x * 64;
    const int tid = threadIdx.x;
    const int tx = tid & 15, ty = tid >> 4;
    const int arow = tid >> 2, aseg = tid & 3;
    const float* Aptr = R + (long)(m0 + arow) * 512 + aseg * 4;
    const float* Bptr = S + (long)(n0 + arow) * 512 + aseg * 4;

    float4 av = *(const float4*)Aptr;
    float4 bv = *(const float4*)Bptr;
    As[0][aseg * 4 + 0][arow] = av.x;
    As[0][aseg * 4 + 1][arow] = av.y;
    As[0][aseg * 4 + 2][arow] = av.z;
    As[0][aseg * 4 + 3][arow] = av.w;
    Bs[0][aseg * 4 + 0][arow] = bv.x;
    Bs[0][aseg * 4 + 1][arow] = bv.y;
    Bs[0][aseg * 4 + 2][arow] = bv.z;
    Bs[0][aseg * 4 + 3][arow] = bv.w;
    __syncthreads();

    float acc[4][4] = {};
    int buf = 0;
    for (int k0 = 0; k0 < 512; k0 += 16) {
        const bool more = (k0 + 16) < 512;
        if (more) {
            av = *(const float4*)(Aptr + k0 + 16);
            bv = *(const float4*)(Bptr + k0 + 16);
        }
#pragma unroll
        for (int kk = 0; kk < 16; kk++) {
            float a[4], b[4];
#pragma unroll
            for (int i2 = 0; i2 < 4; i2++) a[i2] = As[buf][kk][ty * 4 + i2];
#pragma unroll
            for (int j2 = 0; j2 < 4; j2++) b[j2] = Bs[buf][kk][tx * 4 + j2];
#pragma unroll
            for (int i2 = 0; i2 < 4; i2++)
#pragma unroll
                for (int j2 = 0; j2 < 4; j2++) acc[i2][j2] += a[i2] * b[j2];
        }
        if (more) {
            As[buf ^ 1][aseg * 4 + 0][arow] = av.x;
            As[buf ^ 1][aseg * 4 + 1][arow] = av.y;
            As[buf ^ 1][aseg * 4 + 2][arow] = av.z;
            As[buf ^ 1][aseg * 4 + 3][arow] = av.w;
            Bs[buf ^ 1][aseg * 4 + 0][arow] = bv.x;
            Bs[buf ^ 1][aseg * 4 + 1][arow] = bv.y;
            Bs[buf ^ 1][aseg * 4 + 2][arow] = bv.z;
            Bs[buf ^ 1][aseg * 4 + 3][arow] = bv.w;
        }
        __syncthreads();
        buf ^= 1;
    }
#pragma unroll
    for (int i2 = 0; i2 < 4; i2++) {
        const int i = m0 + ty * 4 + i2;
        const float si = stat[i], s2i = stat[256 + i];
#pragma unroll
        for (int j2 = 0; j2 < 4; j2++) {
            const int j = n0 + tx * 4 + j2;
            const float mean = (si + stat[512 + j]) * (1.f / 512.f);
            const float e2 = (s2i + 2.f * acc[i2][j2] + stat[768 + j]) * (1.f / 512.f);
            mrM[i * 256 + j] = mean;
            mrR[i * 256 + j] = rsqrtf(e2 - mean * mean + 1e-5f);
        }
    }
}

// ---------------- batched weight fragize: up to 8 jobs in one launch -------------
struct FragJobs {
    const float* src[8];
    float* dst[8];
    int ldb[8];
    int ntiles[8];
    int start[9];
};
__global__ void __launch_bounds__(256) fragize_all(FragJobs jb)
{
    int job = 0;
#pragma unroll
    for (int u = 1; u < 8; u++) if ((int)blockIdx.x >= jb.start[u]) job = u;
    const float* B = jb.src[job];
    float* F = jb.dst[job];
    const int ldb = jb.ldb[job], ntiles = jb.ntiles[job];
    const int g = (blockIdx.x - jb.start[job]) * 256 + threadIdx.x;
    const int lane = g & 31;
    const int pair = g >> 5;
    const int nt = pair % ntiles;
    const int t = pair / ntiles;
    const int gid = lane >> 2, tig = lane & 3;
    F[(long)g * 2 + 0] = tf32r(B[(long)(t * 8 + tig) * ldb + nt * 8 + gid]);
    F[(long)g * 2 + 1] = tf32r(B[(long)(t * 8 + tig + 4) * ldb + nt * 8 + gid]);
}

// ------------- generic tf32 MMA GEMM, register double-buffered (128 thr) ---------
__global__ void __launch_bounds__(128) mma_gemm(
    const float* __restrict__ A, int lda, long sAz,
    const float* __restrict__ Bf, long sBz, int ntilesTotal,
    float* __restrict__ C, int ldc, long sCz, int K,
    const float* __restrict__ bias, int biasZmask)
{
    __shared__ float As[64][36];
    __shared__ float Bs[4][16][64];
    const int z = blockIdx.z;
    A += (long)z * sAz; Bf += (long)z * sBz; C += (long)z * sCz;
    const int m0 = blockIdx.y * 64, n0 = blockIdx.x * 128;
    const int ntile0 = blockIdx.x * 16;
    const int tid = threadIdx.x;
    const int warp = tid >> 5, lane = tid & 31;
    const int gid = lane >> 2, tig = lane & 3;

    float4 aR[4], bR[8];
#pragma unroll
    for (int it = 0; it < 4; it++) {
        const int idx = it * 128 + tid, row = idx >> 3, seg = idx & 7;
        aR[it] = *(const float4*)(A + (long)(m0 + row) * lda + seg * 4);
    }
#pragma unroll
    for (int it = 0; it < 8; it++) {
        const int idx = it * 128 + tid, ks = idx >> 8, rem = idx & 255;
        const int nt = rem >> 4, f4 = rem & 15;
        bR[it] = *(const float4*)(Bf + (long)ks * ntilesTotal * 64 + (long)(ntile0 + nt) * 64 + f4 * 4);
    }

    float acc[16][4] = {};
    for (int k0 = 0; k0 < K; k0 += 32) {
#pragma unroll
        for (int it = 0; it < 4; it++) {
            const int idx = it * 128 + tid, row = idx >> 3, seg = idx & 7;
            float4 w;
            w.x = tf32r(aR[it].x); w.y = tf32r(aR[it].y);
            w.z = tf32r(aR[it].z); w.w = tf32r(aR[it].w);
            *(float4*)&As[row][seg * 4] = w;
        }
#pragma unroll
        for (int it = 0; it < 8; it++) {
            const int idx = it * 128 + tid, ks = idx >> 8, rem = idx & 255;
            const int nt = rem >> 4, f4 = rem & 15;
            *(float4*)&Bs[ks][nt][f4 * 4] = bR[it];
        }
        __syncthreads();
        if (k0 + 32 < K) {
#pragma unroll
            for (int it = 0; it < 4; it++) {
                const int idx = it * 128 + tid, row = idx >> 3, seg = idx & 7;
                aR[it] = *(const float4*)(A + (long)(m0 + row) * lda + k0 + 32 + seg * 4);
            }
#pragma unroll
            for (int it = 0; it < 8; it++) {
                const int idx = it * 128 + tid, ks = idx >> 8, rem = idx & 255;
                const int nt = rem >> 4, f4 = rem & 15;
                bR[it] = *(const float4*)(Bf + (long)((k0 + 32) / 8 + ks) * ntilesTotal * 64
                                          + (long)(ntile0 + nt) * 64 + f4 * 4);
            }
        }
#pragma unroll
        for (int ks = 0; ks < 4; ks++) {
            const int kc = ks * 8;
            const unsigned a0 = __float_as_uint(As[warp * 16 + gid][kc + tig]);
            const unsigned a1 = __float_as_uint(As[warp * 16 + gid + 8][kc + tig]);
            const unsigned a2 = __float_as_uint(As[warp * 16 + gid][kc + tig + 4]);
            const unsigned a3 = __float_as_uint(As[warp * 16 + gid + 8][kc + tig + 4]);
#pragma unroll
            for (int nt = 0; nt < 16; nt++) {
                const float2 b = *(const float2*)&Bs[ks][nt][lane * 2];
                mma_tf32(acc[nt], a0, a1, a2, a3, __float_as_uint(b.x), __float_as_uint(b.y));
            }
        }
        __syncthreads();
    }
    const int row = m0 + warp * 16 + gid;
    const bool addb = bias && ((biasZmask >> z) & 1);
#pragma unroll
    for (int nt = 0; nt < 16; nt++) {
        const int col = n0 + nt * 8 + tig * 2;
        float b0 = 0.f, b1 = 0.f;
        if (addb) { b0 = bias[col]; b1 = bias[col + 1]; }
        *(float2*)(C + (long)row * ldc + col) = make_float2(acc[nt][0] + b0, acc[nt][1] + b1);
        *(float2*)(C + (long)(row + 8) * ldc + col) = make_float2(acc[nt][2] + b0, acc[nt][3] + b1);
    }
}

// ---------------- transpose: Qt[k][n] from Q[n][k] ----------------
__global__ void __launch_bounds__(256) transpose_kernel(
    const float* __restrict__ Q, float* __restrict__ T)
{
    __shared__ float t[32][33];
    const int bk = blockIdx.x * 32;
    const int bn = blockIdx.y * 32;
    const int tx = threadIdx.x & 31, ty = threadIdx.x >> 5;
#pragma unroll
    for (int r = 0; r < 32; r += 8)
        t[ty + r][tx] = Q[(long)(bn + ty + r) * 512 + bk + tx];
    __syncthreads();
#pragma unroll
    for (int r = 0; r < 32; r += 8)
        T[(long)(bk + ty + r) * 256 + bn + tx] = t[tx][ty + r];
}

// ------- per-row sum / sumsq over TWO matrices (one pair-MLP half) ---------------
__global__ void __launch_bounds__(256) rowstats2_kernel(
    const float* __restrict__ src, float* __restrict__ stat)
{
    const int w = blockIdx.x * 8 + (threadIdx.x >> 5);  // 0..511
    const int lane = threadIdx.x & 31;
    const int mat = w >> 8, row = w & 255;
    const float* p = src + mat * 131072 + row * 512;
    float s = 0.f, s2 = 0.f;
#pragma unroll 4
    for (int k = lane; k < 512; k += 32) { const float v = p[k]; s += v; s2 += v * v; }
    s = warpSum(s); s2 = warpSum(s2);
    if (lane == 0) { stat[mat * 512 + row] = s; stat[mat * 512 + 256 + row] = s2; }
}

// ------- per-pair LN mean / rstd for the ep pair-MLP (bit-stable) ---------------
__global__ void __launch_bounds__(256) meanrstd_half(
    const float* __restrict__ stat, const float* __restrict__ dots,
    float* __restrict__ mrM, float* __restrict__ mrR)
{
    const int i = blockIdx.x, j = threadIdx.x;
    const int idx = i * 256 + j;
    const float m = (stat[i] + stat[512 + j]) * (1.f / 512.f);
    const float e2 = (stat[256 + i] + 2.f * dots[idx] + stat[768 + j]) * (1.f / 512.f);
    mrM[idx] = m;
    mrR[idx] = rsqrtf(e2 - m * m + 1e-5f);
}

// ---------------- edge predictor: 2 dst rows per CTA (fp32) ----------------
__global__ void __launch_bounds__(256) ep2_kernel(
    const float* __restrict__ P, const float* __restrict__ Qt,
    const float* __restrict__ mr,
    const float* __restrict__ gg, const float* __restrict__ bb,
    const float* __restrict__ w2, const float* __restrict__ b2,
    float* __restrict__ outActive, float* __restrict__ adj)
{
    const int i0 = blockIdx.x * 2;
    const int j = threadIdx.x;
    __shared__ float Pi[2][512], gs[512], bs[512], ws[512];
    for (int t = j; t < 512; t += 256) {
        Pi[0][t] = P[(long)i0 * 512 + t];
        Pi[1][t] = P[(long)(i0 + 1) * 512 + t];
        gs[t] = gg[t]; bs[t] = bb[t]; ws[t] = w2[t];
    }
    __syncthreads();
    const float m0 = mr[i0 * 256 + j],       r0 = mr[65536 + i0 * 256 + j];
    const float m1 = mr[(i0 + 1) * 256 + j], r1 = mr[65536 + (i0 + 1) * 256 + j];
    float acc0 = 0.f, acc1 = 0.f;
    for (int k = 0; k < 512; k += 4) {
        const float4 g4 = *(const float4*)&gs[k];
        const float4 b4 = *(const float4*)&bs[k];
        const float4 w4 = *(const float4*)&ws[k];
        const float4 p0 = *(const float4*)&Pi[0][k];
        const float4 p1 = *(const float4*)&Pi[1][k];
        const float q0 = Qt[(k + 0) * 256 + j];
        const float q1 = Qt[(k + 1) * 256 + j];
        const float q2 = Qt[(k + 2) * 256 + j];
        const float q3 = Qt[(k + 3) * 256 + j];
        acc0 += lrelu((p0.x + q0 - m0) * r0 * g4.x + b4.x) * w4.x;
        acc0 += lrelu((p0.y + q1 - m0) * r0 * g4.y + b4.y) * w4.y;
        acc0 += lrelu((p0.z + q2 - m0) * r0 * g4.z + b4.z) * w4.z;
        acc0 += lrelu((p0.w + q3 - m0) * r0 * g4.w + b4.w) * w4.w;
        acc1 += lrelu((p1.x + q0 - m1) * r1 * g4.x + b4.x) * w4.x;
        acc1 += lrelu((p1.y + q1 - m1) * r1 * g4.y + b4.y) * w4.y;
        acc1 += lrelu((p1.z + q2 - m1) * r1 * g4.z + b4.z) * w4.z;
        acc1 += lrelu((p1.w + q3 - m1) * r1 * g4.w + b4.w) * w4.w;
    }
    const float b2v = b2[0];
#pragma unroll
    for (int u = 0; u < 2; u++) {
        const int i = i0 + u;
        const float lg = (u ? acc1 : acc0) + b2v;
        const bool act = (lg > 0.f) && (i != j);
        outActive[i * 256 + j] = act ? 1.f : 0.f;
        adj[j * 256 + i] = (i == j) ? 1.f : (act ? 1.f : 0.f);
    }
}

// --------- fused edge-feature MMA kernel, register double-buffered (lean) --------
__global__ void __launch_bounds__(128) ef_mma_kernel(
    const float* __restrict__ RS, const float* __restrict__ mr,
    const float* __restrict__ gg, const float* __restrict__ bb,
    const float* __restrict__ w2f, const float* __restrict__ b2,
    float* __restrict__ outEF)
{
    const float* S = RS + 131072;
    const int i = blockIdx.y;
    const int j0 = blockIdx.x * 64;
    const int tid = threadIdx.x;
    __shared__ float Ri[512], gs[512], bs[512];
    __shared__ float Hs[64][36];
    __shared__ float Bs[4][16][64];
    __shared__ float mean_s[64], rstd_s[64];
    for (int t = tid; t < 512; t += 128) {
        Ri[t] = RS[i * 512 + t]; gs[t] = gg[t]; bs[t] = bb[t];
    }
    if (tid < 64) {
        mean_s[tid] = mr[131072 + i * 256 + j0 + tid];
        rstd_s[tid] = mr[196608 + i * 256 + j0 + tid];
    }
    const int warp = tid >> 5, lane = tid & 31;
    const int gid = lane >> 2, tig = lane & 3;

    float4 sR[4], wR[8];
#pragma unroll
    for (int it = 0; it < 4; it++) {
        const int idx = it * 128 + tid, row = idx >> 3, seg = idx & 7;
        sR[it] = *(const float4*)(S + (long)(j0 + row) * 512 + seg * 4);
    }
#pragma unroll
    for (int it = 0; it < 8; it++) {
        const int idx = it * 128 + tid, ks = idx >> 8, rem = idx & 255;
        const int nt = rem >> 4, f4 = rem & 15;
        wR[it] = *(const float4*)(w2f + (long)ks * 1024 + nt * 64 + f4 * 4);
    }
    __syncthreads();

    float acc[16][4] = {};
    for (int k0 = 0; k0 < 512; k0 += 32) {
#pragma unroll
        for (int it = 0; it < 4; it++) {
            const int idx = it * 128 + tid, row = idx >> 3, seg = idx & 7;
            const int k = k0 + seg * 4;
            const float4 r4 = *(const float4*)&Ri[k];
            const float4 g4 = *(const float4*)&gs[k];
            const float4 b4 = *(const float4*)&bs[k];
            const float m = mean_s[row], rs = rstd_s[row];
            float4 h;
            h.x = tf32r(lrelu((r4.x + sR[it].x - m) * rs * g4.x + b4.x));
            h.y = tf32r(lrelu((r4.y + sR[it].y - m) * rs * g4.y + b4.y));
            h.z = tf32r(lrelu((r4.z + sR[it].z - m) * rs * g4.z + b4.z));
            h.w = tf32r(lrelu((r4.w + sR[it].w - m) * rs * g4.w + b4.w));
            *(float4*)&Hs[row][seg * 4] = h;
        }
#pragma unroll
        for (int it = 0; it < 8; it++) {
            const int idx = it * 128 + tid, ks = idx >> 8, rem = idx & 255;
            const int nt = rem >> 4, f4 = rem & 15;
            *(float4*)&Bs[ks][nt][f4 * 4] = wR[it];
        }
        __syncthreads();
        if (k0 + 32 < 512) {
#pragma unroll
            for (int it = 0; it < 4; it++) {
                const int idx = it * 128 + tid, row = idx >> 3, seg = idx & 7;
                sR[it] = *(const float4*)(S + (long)(j0 + row) * 512 + k0 + 32 + seg * 4);
            }
#pragma unroll
            for (int it = 0; it < 8; it++) {
                const int idx = it * 128 + tid, ks = idx >> 8, rem = idx & 255;
                const int nt = rem >> 4, f4 = rem & 15;
                wR[it] = *(const float4*)(w2f + (long)((k0 + 32) / 8 + ks) * 1024 + nt * 64 + f4 * 4);
            }
        }
#pragma unroll
        for (int ks = 0; ks < 4; ks++) {
            const int kc = ks * 8;
            const unsigned a0 = __float_as_uint(Hs[warp * 16 + gid][kc + tig]);
            const unsigned a1 = __float_as_uint(Hs[warp * 16 + gid + 8][kc + tig]);
            const unsigned a2 = __float_as_uint(Hs[warp * 16 + gid][kc + tig + 4]);
            const unsigned a3 = __float_as_uint(Hs[warp * 16 + gid + 8][kc + tig + 4]);
#pragma unroll
            for (int nt = 0; nt < 16; nt++) {
                const float2 b = *(const float2*)&Bs[ks][nt][lane * 2];
                mma_tf32(acc[nt], a0, a1, a2, a3, __float_as_uint(b.x), __float_as_uint(b.y));
            }
        }
        __syncthreads();
    }
    const int row = j0 + warp * 16 + gid;
#pragma unroll
    for (int nt = 0; nt < 16; nt++) {
        const int col = nt * 8 + tig * 2;
        const float b0 = b2[col], b1 = b2[col + 1];
        float* dst = outEF + ((long)i * 256 + row) * 128 + col;
        *(float2*)dst = make_float2(acc[nt][0] + b0, acc[nt][1] + b1);
        *(float2*)(dst + 8 * 128) = make_float2(acc[nt][2] + b0, acc[nt][3] + b1);
    }
}

// --------- GAT s-GEMM: writes s directly in B-frag layout + a_src/a_dst partials -
__global__ void __launch_bounds__(128) gat_s_mma(
    const float* __restrict__ A,
    const float* __restrict__ Bf,
    const float* __restrict__ a_src, const float* __restrict__ a_dst,
    float* __restrict__ Sf,
    float* __restrict__ asdp)
{
    __shared__ float As[64][36];
    __shared__ float Bs[4][16][64];
    const int m0 = blockIdx.y * 64;
    const int ntile0 = blockIdx.x * 16;
    const int head = blockIdx.x >> 2;
    const int xq = blockIdx.x & 3;
    const int nh0 = xq * 128;
    const int tid = threadIdx.x;
    const int warp = tid >> 5, lane = tid & 31;
    const int gid = lane >> 2, tig = lane & 3;

    float4 aR[4], bR[8];
#pragma unroll
    for (int it = 0; it < 4; it++) {
        const int idx = it * 128 + tid, row = idx >> 3, seg = idx & 7;
        aR[it] = *(const float4*)(A + (long)(m0 + row) * 512 + seg * 4);
    }
#pragma unroll
    for (int it = 0; it < 8; it++) {
        const int idx = it * 128 + tid, ks = idx >> 8, rem = idx & 255;
        const int nt = rem >> 4, f4 = rem & 15;
        bR[it] = *(const float4*)(Bf + (long)ks * 256 * 64 + (long)(ntile0 + nt) * 64 + f4 * 4);
    }

    float acc[16][4] = {};
    for (int k0 = 0; k0 < 512; k0 += 32) {
#pragma unroll
        for (int it = 0; it < 4; it++) {
            const int idx = it * 128 + tid, row = idx >> 3, seg = idx & 7;
            float4 w;
            w.x = tf32r(aR[it].x); w.y = tf32r(aR[it].y);
            w.z = tf32r(aR[it].z); w.w = tf32r(aR[it].w);
            *(float4*)&As[row][seg * 4] = w;
        }
#pragma unroll
        for (int it = 0; it < 8; it++) {
            const int idx = it * 128 + tid, ks = idx >> 8, rem = idx & 255;
            const int nt = rem >> 4, f4 = rem & 15;
            *(float4*)&Bs[ks][nt][f4 * 4] = bR[it];
        }
        __syncthreads();
        if (k0 + 32 < 512) {
#pragma unroll
            for (int it = 0; it < 4; it++) {
                const int idx = it * 128 + tid, row = idx >> 3, seg = idx & 7;
                aR[it] = *(const float4*)(A + (long)(m0 + row) * 512 + k0 + 32 + seg * 4);
            }
#pragma unroll
            for (int it = 0; it < 8; it++) {
                const int idx = it * 128 + tid, ks = idx >> 8, rem = idx & 255;
                const int nt = rem >> 4, f4 = rem & 15;
                bR[it] = *(const float4*)(Bf + (long)((k0 + 32) / 8 + ks) * 256 * 64
                                          + (long)(ntile0 + nt) * 64 + f4 * 4);
            }
        }
#pragma unroll
        for (int ks = 0; ks < 4; ks++) {
            const int kc = ks * 8;
            const unsigned a0 = __float_as_uint(As[warp * 16 + gid][kc + tig]);
            const unsigned a1 = __float_as_uint(As[warp * 16 + gid + 8][kc + tig]);
            const unsigned a2 = __float_as_uint(As[warp * 16 + gid][kc + tig + 4]);
            const unsigned a3 = __float_as_uint(As[warp * 16 + gid + 8][kc + tig + 4]);
#pragma unroll
            for (int nt = 0; nt < 16; nt++) {
                const float2 b = *(const float2*)&Bs[ks][nt][lane * 2];
                mma_tf32(acc[nt], a0, a1, a2, a3, __float_as_uint(b.x), __float_as_uint(b.y));
            }
        }
        __syncthreads();
    }
    const int row = m0 + warp * 16 + gid;
    const int r1 = row + 8;
    const int t0 = row >> 3, kk0 = row & 7;
    const int t1 = r1 >> 3, kk1 = r1 & 7;
    float* SfH = Sf + head * 131072;
    const float* asr = a_src + head * 512;
    const float* adr = a_dst + head * 512;
    float ds0 = 0.f, dd0 = 0.f, ds1 = 0.f, dd1 = 0.f;
#pragma unroll
    for (int nt = 0; nt < 16; nt++) {
        const int c0 = nh0 + nt * 8 + tig * 2;
#pragma unroll
        for (int u = 0; u < 2; u++) {
            const int ch = c0 + u;
            const float asv = asr[ch], adv = adr[ch];
            const float v0 = acc[nt][u];
            const float v1 = acc[nt][2 + u];
            ds0 += v0 * asv; dd0 += v0 * adv;
            ds1 += v1 * asv; dd1 += v1 * adv;
            const int ntf = ch >> 3, gidf = ch & 7;
            SfH[((t0 * 64 + ntf) * 32 + gidf * 4 + (kk0 & 3)) * 2 + (kk0 >> 2)] = tf32r(v0);
            SfH[((t1 * 64 + ntf) * 32 + gidf * 4 + (kk1 & 3)) * 2 + (kk1 >> 2)] = tf32r(v1);
        }
    }
    ds0 += __shfl_xor_sync(FULLMASK, ds0, 1); ds0 += __shfl_xor_sync(FULLMASK, ds0, 2);
    dd0 += __shfl_xor_sync(FULLMASK, dd0, 1); dd0 += __shfl_xor_sync(FULLMASK, dd0, 2);
    ds1 += __shfl_xor_sync(FULLMASK, ds1, 1); ds1 += __shfl_xor_sync(FULLMASK, ds1, 2);
    dd1 += __shfl_xor_sync(FULLMASK, dd1, 1); dd1 += __shfl_xor_sync(FULLMASK, dd1, 2);
    if (tig == 0) {
        asdp[(row * 4 + head) * 4 + xq] = ds0;
        asdp[4096 + (row * 4 + head) * 4 + xq] = dd0;
        asdp[(r1 * 4 + head) * 4 + xq] = ds1;
        asdp[4096 + (r1 * 4 + head) * 4 + xq] = dd1;
    }
}

// --------- attention stats: sum partials, per-(i,head) max and 1/Z --------------
__global__ void __launch_bounds__(256) attn_stats_kernel(
    const float* __restrict__ asdp, const float* __restrict__ adj,
    float* __restrict__ asd, float* __restrict__ stats)
{
    __shared__ float sm[8];
    __shared__ float adi[4];
    const int i = blockIdx.x, j = threadIdx.x;
    const int warp = j >> 5, lane = j & 31;
    float asv[4];
#pragma unroll
    for (int h = 0; h < 4; h++) {
        const int b = (j * 4 + h) * 4;
        const float s = asdp[b] + asdp[b + 1] + asdp[b + 2] + asdp[b + 3];
        const float d = asdp[4096 + b] + asdp[4096 + b + 1] + asdp[4096 + b + 2] + asdp[4096 + b + 3];
        asv[h] = s;
        asd[j * 4 + h] = s;
        asd[1024 + j * 4 + h] = d;
        if (j == i) adi[h] = d;
    }
    __syncthreads();
    const bool on = adj[i * 256 + j] > 0.5f;
#pragma unroll
    for (int h = 0; h < 4; h++) {
        const float lg = lrelu(adi[h] + asv[h]);
        float v = on ? lg : -1e30f;
        v = warpMax(v);
        if (lane == 0) sm[warp] = v;
        __syncthreads();
        const float m = fmaxf(fmaxf(fmaxf(sm[0], sm[1]), fmaxf(sm[2], sm[3])),
                              fmaxf(fmaxf(sm[4], sm[5]), fmaxf(sm[6], sm[7])));
        __syncthreads();
        const float w = on ? __expf(lg - m) : 0.f;
        float ws = warpSum(w);
        if (lane == 0) sm[warp] = ws;
        __syncthreads();
        const float Z = sm[0] + sm[1] + sm[2] + sm[3] + sm[4] + sm[5] + sm[6] + sm[7];
        __syncthreads();
        if (j == 0) { stats[i * 8 + h * 2] = m; stats[i * 8 + h * 2 + 1] = 1.f / Z; }
    }
}

// --------- fused aggregation: alpha computed on the fly in A staging -------------
__global__ void __launch_bounds__(128) agg_mma(
    const float* __restrict__ adj, const float* __restrict__ asd,
    const float* __restrict__ stats, const float* __restrict__ Sf,
    float* __restrict__ agg)
{
    __shared__ float As[64][36];
    __shared__ float Bs[4][16][64];
    __shared__ float m_s[64], iz_s[64], ad_s[64];
    const int head = blockIdx.z;
    const int i0 = blockIdx.y * 64;
    const int n0 = blockIdx.x * 128;
    const int ntile0 = blockIdx.x * 16;
    const int tid = threadIdx.x;
    const int warp = tid >> 5, lane = tid & 31;
    const int gid = lane >> 2, tig = lane & 3;
    const float* Bfh = Sf + head * 131072;

    if (tid < 64) {
        const int r = i0 + tid;
        m_s[tid] = stats[r * 8 + head * 2];
        iz_s[tid] = stats[r * 8 + head * 2 + 1];
        ad_s[tid] = asd[1024 + r * 4 + head];
    }

    float4 jR[4], bR[8];
#pragma unroll
    for (int it = 0; it < 4; it++) {
        const int idx = it * 128 + tid, row = idx >> 3, seg = idx & 7;
        jR[it] = *(const float4*)(adj + (long)(i0 + row) * 256 + seg * 4);
    }
#pragma unroll
    for (int it = 0; it < 8; it++) {
        const int idx = it * 128 + tid, ks = idx >> 8, rem = idx & 255;
        const int nt = rem >> 4, f4 = rem & 15;
        bR[it] = *(const float4*)(Bfh + (long)ks * 64 * 64 + (long)(ntile0 + nt) * 64 + f4 * 4);
    }
    __syncthreads();

    float acc[16][4] = {};
    for (int k0 = 0; k0 < 256; k0 += 32) {
#pragma unroll
        for (int it = 0; it < 4; it++) {
            const int idx = it * 128 + tid, row = idx >> 3, seg = idx & 7;
            float av[4];
            *(float4*)av = jR[it];
            const float adv = ad_s[row], mm = m_s[row], iz = iz_s[row];
#pragma unroll
            for (int u = 0; u < 4; u++) {
                const int jj = k0 + seg * 4 + u;
                const float lg = lrelu(adv + asd[jj * 4 + head]);
                const float val = (av[u] > 0.5f) ? __expf(lg - mm) * iz : 0.f;
                As[row][seg * 4 + u] = tf32r(val);
            }
        }
#pragma unroll
        for (int it = 0; it < 8; it++) {
            const int idx = it * 128 + tid, ks = idx >> 8, rem = idx & 255;
            const int nt = rem >> 4, f4 = rem & 15;
            *(float4*)&Bs[ks][nt][f4 * 4] = bR[it];
        }
        __syncthreads();
        if (k0 + 32 < 256) {
#pragma unroll
            for (int it = 0; it < 4; it++) {
                const int idx = it * 128 + tid, row = idx >> 3, seg = idx & 7;
                jR[it] = *(const float4*)(adj + (long)(i0 + row) * 256 + k0 + 32 + seg * 4);
            }
#pragma unroll
            for (int it = 0; it < 8; it++) {
                const int idx = it * 128 + tid, ks = idx >> 8, rem = idx & 255;
                const int nt = rem >> 4, f4 = rem & 15;
                bR[it] = *(const float4*)(Bfh + (long)((k0 + 32) / 8 + ks) * 64 * 64
                                          + (long)(ntile0 + nt) * 64 + f4 * 4);
            }
        }
#pragma unroll
        for (int ks = 0; ks < 4; ks++) {
            const int kc = ks * 8;
            const unsigned a0 = __float_as_uint(As[warp * 16 + gid][kc + tig]);
            const unsigned a1 = __float_as_uint(As[warp * 16 + gid + 8][kc + tig]);
            const unsigned a2 = __float_as_uint(As[warp * 16 + gid][kc + tig + 4]);
            const unsigned a3 = __float_as_uint(As[warp * 16 + gid + 8][kc + tig + 4]);
#pragma unroll
            for (int nt = 0; nt < 16; nt++) {
                const float2 b = *(const float2*)&Bs[ks][nt][lane * 2];
                mma_tf32(acc[nt], a0, a1, a2, a3, __float_as_uint(b.x), __float_as_uint(b.y));
            }
        }
        __syncthreads();
    }
    const int row = i0 + warp * 16 + gid;
#pragma unroll
    for (int nt = 0; nt < 16; nt++) {
        const int col = head * 512 + n0 + nt * 8 + tig * 2;
        *(float2*)(agg + (long)row * 2048 + col) = make_float2(acc[nt][0], acc[nt][1]);
        *(float2*)(agg + (long)(row + 8) * 2048 + col) = make_float2(acc[nt][2], acc[nt][3]);
    }
}

// ---------------- mean over heads + bias + LeakyReLU ----------------
__global__ void __launch_bounds__(256) combine_kernel(
    const float* __restrict__ agg, const float* __restrict__ gb, float* __restrict__ x)
{
    const int i = blockIdx.x;
    for (int c = threadIdx.x; c < 512; c += 256) {
        const long b = (long)i * 2048;
        const float v = 0.25f * (agg[b + c] + agg[b + 512 + c] + agg[b + 1024 + c] + agg[b + 1536 + c]) + gb[c];
        x[i * 512 + c] = lrelu(v);
    }
}

// ---------------- row LayerNorm + LeakyReLU ----------------
__global__ void __launch_bounds__(256) ln_lrelu_kernel(
    float* __restrict__ h, const float* __restrict__ gg, const float* __restrict__ bb)
{
    __shared__ float sm[8];
    const int i = blockIdx.x;
    const int t = threadIdx.x;
    const int warp = t >> 5, lane = t & 31;
    float* row = h + (long)i * 512;
    const float v0 = row[t], v1 = row[t + 256];
    float s = warpSum(v0 + v1);
    if (lane == 0) sm[warp] = s;
    __syncthreads();
    const float mean = (sm[0] + sm[1] + sm[2] + sm[3] + sm[4] + sm[5] + sm[6] + sm[7]) * (1.f / 512.f);
    __syncthreads();
    const float d0 = v0 - mean, d1 = v1 - mean;
    float s2 = warpSum(d0 * d0 + d1 * d1);
    if (lane == 0) sm[warp] = s2;
    __syncthreads();
    const float var = (sm[0] + sm[1] + sm[2] + sm[3] + sm[4] + sm[5] + sm[6] + sm[7]) * (1.f / 512.f);
    const float rstd = rsqrtf(var + 1e-5f);
    row[t] = lrelu(d0 * rstd * gg[t] + bb[t]);
    row[t + 256] = lrelu(d1 * rstd * gg[t + 256] + bb[t + 256]);
}

// ===================================================================================
extern "C" void kernel_launch(void* const* d_in, const int* in_sizes, int n_in,
                              void* d_out, int out_size)
{
    (void)in_sizes; (void)n_in; (void)out_size;
    const float* emb     = (const float*)d_in[0];
    const float* ep_w1   = (const float*)d_in[1];
    const float* ep_b1   = (const float*)d_in[2];
    const float* ep_g    = (const float*)d_in[3];
    const float* ep_beta = (const float*)d_in[4];
    const float* ep_w2   = (const float*)d_in[5];
    const float* ep_b2   = (const float*)d_in[6];
    const float* ef_w1   = (const float*)d_in[7];
    const float* ef_b1   = (const float*)d_in[8];
    const float* ef_g    = (const float*)d_in[9];
    const float* ef_beta = (const float*)d_in[10];
    const float* ef_w2   = (const float*)d_in[11];
    const float* ef_b2   = (const float*)d_in[12];
    const float* gat_W   = (const float*)d_in[13];
    const float* gat_as  = (const float*)d_in[14];
    const float* gat_ad  = (const float*)d_in[15];
    const float* gat_b   = (const float*)d_in[16];
    const float* op_w1   = (const float*)d_in[17];
    const float* op_b1   = (const float*)d_in[18];
    const float* op_g    = (const float*)d_in[19];
    const float* op_beta = (const float*)d_in[20];
    const float* op_w2   = (const float*)d_in[21];
    const float* op_b2   = (const float*)d_in[22];

    float *pPQ, *pRS, *pStat, *pT, *pDot, *pMr, *pAdj, *pAsdP, *pAsd, *pStats,
          *pAgg, *pX, *pH, *pW2f, *pW1f, *pWf, *pSf, *pOpf;
    cudaGetSymbolAddress((void**)&pPQ, g_PQ);
    cudaGetSymbolAddress((void**)&pRS, g_RS);
    cudaGetSymbolAddress((void**)&pStat, g_stat);
    cudaGetSymbolAddress((void**)&pT, g_t);
    cudaGetSymbolAddress((void**)&pDot, g_dot);
    cudaGetSymbolAddress((void**)&pMr, g_mr);
    cudaGetSymbolAddress((void**)&pAdj, g_adj);
    cudaGetSymbolAddress((void**)&pAsdP, g_asdp);
    cudaGetSymbolAddress((void**)&pAsd, g_asd);
    cudaGetSymbolAddress((void**)&pStats, g_stats);
    cudaGetSymbolAddress((void**)&pAgg, g_agg);
    cudaGetSymbolAddress((void**)&pX, g_x);
    cudaGetSymbolAddress((void**)&pH, g_h);
    cudaGetSymbolAddress((void**)&pW2f, g_w2frag);
    cudaGetSymbolAddress((void**)&pW1f, g_w1frag);
    cudaGetSymbolAddress((void**)&pWf, g_wfrag);
    cudaGetSymbolAddress((void**)&pSf, g_sfrag);
    cudaGetSymbolAddress((void**)&pOpf, g_opfrag);

    float* out0      = (float*)d_out;
    float* outActive = out0 + 256 * 512;
    float* outEF     = outActive + 256 * 256;

    // Side streams at lowest priority (proven-neutral-or-better in R15).
    static cudaStream_t s1 = nullptr, s2 = nullptr;
    static cudaEvent_t eOrigin = nullptr, eS0 = nullptr, eEF = nullptr;
    if (!s1) {
        int leastPrio = 0, greatestPrio = 0;
        cudaDeviceGetStreamPriorityRange(&leastPrio, &greatestPrio);
        cudaStreamCreateWithPriority(&s1, cudaStreamNonBlocking, leastPrio);
        cudaStreamCreateWithPriority(&s2, cudaStreamNonBlocking, leastPrio);
        cudaEventCreateWithFlags(&eOrigin, cudaEventDisableTiming);
        cudaEventCreateWithFlags(&eS0, cudaEventDisableTiming);
        cudaEventCreateWithFlags(&eEF, cudaEventDisableTiming);
    }

    cudaEventRecord(eOrigin, 0);
    cudaStreamWaitEvent(s1, eOrigin, 0);
    cudaStreamWaitEvent(s2, eOrigin, 0);

    const int BIG = 0x7fffffff;

    // ---- s1 (low prio): ef branch: fragA -> RS -> rowstats -> dotmr -> ef_mma ----
    FragJobs ja;
    ja.src[0] = ef_w1;             ja.dst[0] = pW1f;          ja.ldb[0] = 512; ja.ntiles[0] = 64;
    ja.src[1] = ef_w1 + 512 * 512; ja.dst[1] = pW1f + 262144; ja.ldb[1] = 512; ja.ntiles[1] = 64;
    ja.src[2] = ef_w2;             ja.dst[2] = pW2f;          ja.ldb[2] = 128; ja.ntiles[2] = 16;
    for (int u = 3; u < 8; u++) { ja.src[u] = ef_w2; ja.dst[u] = pW2f; ja.ldb[u] = 128; ja.ntiles[u] = 16; }
    ja.start[0] = 0; ja.start[1] = 512; ja.start[2] = 1024;
    for (int u = 3; u < 9; u++) ja.start[u] = BIG;
    fragize_all<<<1152, 256, 0, s1>>>(ja);
    mma_gemm<<<dim3(4, 4, 2), 128, 0, s1>>>(emb, 512, 0, pW1f, 262144, 64,
                                            pRS, 512, 131072, 512, ef_b1, 0b10);
    rowstats2_kernel<<<64, 256, 0, s1>>>(pRS, pStat + 1024);
    dotmr_kernel<<<dim3(4, 4), 256, 0, s1>>>(pRS, pRS + 131072, pStat + 1024,
                                             pMr + 131072, pMr + 196608);
    ef_mma_kernel<<<dim3(4, 256), 128, 0, s1>>>(pRS, pMr, ef_g, ef_beta, pW2f, ef_b2, outEF);
    cudaEventRecord(eEF, s1);

    // ---- s2 (low prio): GAT/op weight frags, then layer-0 gat_s_mma ----
    FragJobs jbb;
    jbb.src[0] = op_w1;                  jbb.dst[0] = pOpf;           jbb.ldb[0] = 512;  jbb.ntiles[0] = 64;
    jbb.src[1] = op_w2;                  jbb.dst[1] = pOpf + 262144;  jbb.ldb[1] = 512;  jbb.ntiles[1] = 64;
    jbb.src[2] = gat_W;                  jbb.dst[2] = pWf;            jbb.ldb[2] = 2048; jbb.ntiles[2] = 256;
    jbb.src[3] = gat_W + 512 * 2048;     jbb.dst[3] = pWf + 1048576;  jbb.ldb[3] = 2048; jbb.ntiles[3] = 256;
    jbb.src[4] = gat_W + 2 * 512 * 2048; jbb.dst[4] = pWf + 2097152;  jbb.ldb[4] = 2048; jbb.ntiles[4] = 256;
    for (int u = 5; u < 8; u++) { jbb.src[u] = op_w1; jbb.dst[u] = pOpf; jbb.ldb[u] = 512; jbb.ntiles[u] = 64; }
    jbb.start[0] = 0; jbb.start[1] = 512; jbb.start[2] = 1024; jbb.start[3] = 3072;
    jbb.start[4] = 5120;
    for (int u = 5; u < 9; u++) jbb.start[u] = BIG;
    fragize_all<<<7168, 256, 0, s2>>>(jbb);
    gat_s_mma<<<dim3(16, 4), 128, 0, s2>>>(emb, pWf, gat_as, gat_ad, pSf, pAsdP);
    cudaEventRecord(eS0, s2);

    // ---- main (default prio): complete ep branch (fp32, bit-stable) ----
    gemm_kernel<<<dim3(8, 4, 2), 256>>>(emb, 512, 0, ep_w1, 512, 512 * 512,
                                        pPQ, 512, 256 * 512, ep_b1, 0b10, 512);
    transpose_kernel<<<dim3(16, 8), 256>>>(pPQ + 131072, pT);
    gemm_kernel<<<dim3(4, 4, 1), 256>>>(pPQ, 512, 0, pT, 256, 0,
                                        pDot, 256, 0, nullptr, 0, 512);
    rowstats2_kernel<<<64, 256>>>(pPQ, pStat);
    meanrstd_half<<<256, 256>>>(pStat, pDot, pMr, pMr + 65536);
    ep2_kernel<<<128, 256>>>(pPQ, pT, pMr, ep_g, ep_beta, ep_w2, ep_b2, outActive, pAdj);

    // ---- main: GAT stack (layer-0 s-GEMM already done on s2) ----
    cudaStreamWaitEvent(0, eS0, 0);
    attn_stats_kernel<<<256, 256>>>(pAsdP, pAdj, pAsd, pStats);
    agg_mma<<<dim3(4, 4, 4), 128>>>(pAdj, pAsd, pStats, pSf, pAgg);
    combine_kernel<<<256, 256>>>(pAgg, gat_b, pX);
    for (int l = 1; l < 3; l++) {
        gat_s_mma<<<dim3(16, 4), 128>>>(pX, pWf + (long)l * 1048576,
                                        gat_as + l * 2048, gat_ad + l * 2048, pSf, pAsdP);
        attn_stats_kernel<<<256, 256>>>(pAsdP, pAdj, pAsd, pStats);
        agg_mma<<<dim3(4, 4, 4), 128>>>(pAdj, pAsd, pStats, pSf, pAgg);
        combine_kernel<<<256, 256>>>(pAgg, gat_b + l * 512, pX);
    }

    // ---- main: output projection ----
    mma_gemm<<<dim3(4, 4, 1), 128>>>(pX, 512, 0, pOpf, 0, 64, pH, 512, 0, 512, op_b1, 1);
    ln_lrelu_kernel<<<256, 256>>>(pH, op_g, op_beta);
    mma_gemm<<<dim3(4, 4, 1), 128>>>(pH, 512, 0, pOpf + 262144, 0, 64, out0, 512, 0, 512, op_b2, 1);

    // ---- join ef branch before returning ----
    cudaStreamWaitEvent(0, eEF, 0);
}